// round 3
// baseline (speedup 1.0000x reference)
#include <cuda_runtime.h>

// LR_23029614641373: logit = W[u] + W[6040 + m] + b; out = [1-p, p]
// B = 4,194,304 rows. W (9923 floats, 39.7 KB) staged in SMEM (LDS gathers,
// ~3.4 avg bank-conflict degree << ~30 L1 wavefronts for scattered LDG).
// Sigmoid via MUFU tanh.approx: p = 0.5 + 0.5*tanh(l/2)  (1 MUFU/row
// instead of EX2+RCP = 2+). 4 rows per thread per iteration.

#define N_USERS  6040
#define TABLE    9923
#define NTHREADS 512
#define NBLK_SM  4

__device__ __forceinline__ float tanh_fast(float x) {
    float y;
    asm("tanh.approx.f32 %0, %1;" : "=f"(y) : "f"(x));
    return y;
}

// two rows from one int4 -> one float4 {1-p0, p0, 1-p1, p1}
__device__ __forceinline__ float4 two_rows(const float* __restrict__ sw,
                                           int4 v, float hbias) {
    // h = l/2 = 0.5*(w_u + w_m) + b/2
    float h0 = 0.5f * (sw[v.x] + sw[N_USERS + v.y]) + hbias;
    float h1 = 0.5f * (sw[v.z] + sw[N_USERS + v.w]) + hbias;
    float t0 = tanh_fast(h0);
    float t1 = tanh_fast(h1);
    return make_float4(fmaf(-0.5f, t0, 0.5f), fmaf(0.5f, t0, 0.5f),
                       fmaf(-0.5f, t1, 0.5f), fmaf(0.5f, t1, 0.5f));
}

__global__ void __launch_bounds__(NTHREADS, NBLK_SM) lr_smem_kernel(
    const int4* __restrict__ x2,      // [n2] two (u,m) rows per int4
    const float* __restrict__ w,      // [9923]
    const float* __restrict__ bptr,   // [1]
    float4* __restrict__ out,         // [n2]
    int n4)                           // groups of 2 int4 (4 rows)
{
    __shared__ float sw[TABLE];
    #pragma unroll
    for (int i = threadIdx.x; i < TABLE; i += NTHREADS)
        sw[i] = w[i];
    __syncthreads();

    const float hbias = 0.5f * __ldg(bptr);
    const int stride = gridDim.x * blockDim.x;

    for (int i = blockIdx.x * blockDim.x + threadIdx.x; i < n4; i += stride) {
        int4 va = x2[2 * i];
        int4 vb = x2[2 * i + 1];
        float4 ra = two_rows(sw, va, hbias);
        float4 rb = two_rows(sw, vb, hbias);
        out[2 * i]     = ra;
        out[2 * i + 1] = rb;
    }
}

// Cleanup for rows not covered by the 4-row main kernel (0..3 rows).
__global__ void lr_tail_kernel(
    const int2* __restrict__ x,
    const float* __restrict__ w,
    const float* __restrict__ bptr,
    float2* __restrict__ out,
    int start, int n)
{
    int i = start + blockIdx.x * blockDim.x + threadIdx.x;
    if (i >= n) return;
    int2 v = x[i];
    float h = 0.5f * (__ldg(w + v.x) + __ldg(w + N_USERS + v.y) + __ldg(bptr));
    float t = tanh_fast(h);
    out[i] = make_float2(fmaf(-0.5f, t, 0.5f), fmaf(0.5f, t, 0.5f));
}

extern "C" void kernel_launch(void* const* d_in, const int* in_sizes, int n_in,
                              void* d_out, int out_size)
{
    const int*   x = (const int*)d_in[0];     // [B, 2] int32
    const float* W = (const float*)d_in[1];   // [1, 9923]
    const float* b = (const float*)d_in[2];   // [1]
    float* out = (float*)d_out;               // [B, 2]

    int B  = in_sizes[0] / 2;   // rows
    int n4 = B / 4;             // 4-row groups

    if (n4 > 0) {
        int max_blocks = 148 * NBLK_SM;
        int blocks = (n4 + NTHREADS - 1) / NTHREADS;
        if (blocks > max_blocks) blocks = max_blocks;
        lr_smem_kernel<<<blocks, NTHREADS>>>(
            (const int4*)x, W, b, (float4*)out, n4);
    }
    int done = 4 * n4;
    if (done < B) {
        lr_tail_kernel<<<1, 32>>>(
            (const int2*)x, W, b, (float2*)out, done, B);
    }
}

// round 4
// speedup vs baseline: 1.0137x; 1.0137x over previous
#include <cuda_runtime.h>

// LR_23029614641373: logit = W[u] + W[6040+m] + b; out = [1-p, p]
// B = 4,194,304. W (9923 floats) staged in SMEM pre-scaled by 0.5.
// p = 0.5 + 0.5*tanh(l/2) via MUFU tanh.approx (1 MUFU/row).
// Coalesced: 1 int4 (2 rows) per thread per grid-stride iter,
// 1 float4 store. (R3's 2-int4/thread stride-2 pattern doubled L1
// wavefronts — reverted.)

#define N_USERS  6040
#define TABLE    9923
#define NTHREADS 512
#define NBLK_SM  4

__device__ __forceinline__ float tanh_fast(float x) {
    float y;
    asm("tanh.approx.f32 %0, %1;" : "=f"(y) : "f"(x));
    return y;
}

__global__ void __launch_bounds__(NTHREADS, NBLK_SM) lr_smem_kernel(
    const int4* __restrict__ x2,      // [n2] two (u,m) rows per int4
    const float* __restrict__ w,      // [9923]
    const float* __restrict__ bptr,   // [1]
    float4* __restrict__ out,         // [n2] {1-p0,p0,1-p1,p1}
    int n2)
{
    __shared__ float sw[TABLE];       // holds 0.5*W
    for (int i = threadIdx.x; i < TABLE; i += NTHREADS)
        sw[i] = 0.5f * w[i];
    __syncthreads();

    const float hbias = 0.5f * __ldg(bptr);
    const int stride = gridDim.x * blockDim.x;

    for (int i = blockIdx.x * blockDim.x + threadIdx.x; i < n2; i += stride) {
        int4 v = x2[i];

        // h = l/2 ; table already holds 0.5*w
        float h0 = sw[v.x] + sw[N_USERS + v.y] + hbias;
        float h1 = sw[v.z] + sw[N_USERS + v.w] + hbias;
        float t0 = tanh_fast(h0);
        float t1 = tanh_fast(h1);

        out[i] = make_float4(fmaf(-0.5f, t0, 0.5f), fmaf(0.5f, t0, 0.5f),
                             fmaf(-0.5f, t1, 0.5f), fmaf(0.5f, t1, 0.5f));
    }
}

// Rare odd-row tail (B is even in this dataset).
__global__ void lr_tail_kernel(
    const int2* __restrict__ x,
    const float* __restrict__ w,
    const float* __restrict__ bptr,
    float2* __restrict__ out,
    int start, int n)
{
    int i = start + blockIdx.x * blockDim.x + threadIdx.x;
    if (i >= n) return;
    int2 v = x[i];
    float h = 0.5f * (__ldg(w + v.x) + __ldg(w + N_USERS + v.y) + __ldg(bptr));
    float t = tanh_fast(h);
    out[i] = make_float2(fmaf(-0.5f, t, 0.5f), fmaf(0.5f, t, 0.5f));
}

extern "C" void kernel_launch(void* const* d_in, const int* in_sizes, int n_in,
                              void* d_out, int out_size)
{
    const int*   x = (const int*)d_in[0];     // [B, 2] int32
    const float* W = (const float*)d_in[1];   // [1, 9923]
    const float* b = (const float*)d_in[2];   // [1]
    float* out = (float*)d_out;               // [B, 2]

    int B  = in_sizes[0] / 2;   // rows
    int n2 = B / 2;             // int4 groups (2 rows each)

    if (n2 > 0) {
        int max_blocks = 148 * NBLK_SM;
        int blocks = (n2 + NTHREADS - 1) / NTHREADS;
        if (blocks > max_blocks) blocks = max_blocks;
        lr_smem_kernel<<<blocks, NTHREADS>>>(
            (const int4*)x, W, b, (float4*)out, n2);
    }
    if (B & 1) {
        lr_tail_kernel<<<1, 32>>>(
            (const int2*)x, W, b, (float2*)out, 2 * n2, B);
    }
}